// round 6
// baseline (speedup 1.0000x reference)
#include <cuda_runtime.h>
#include <math.h>

#define BB    128
#define LSEQ  4096
#define NF    2049
#define L1E   1025
#define L2E   513
#define OUTS  256

// ---------------- scratch (device globals; no allocations allowed) ----------
__device__ float g_fft[BB * 2 * NF];          // windowed rfft, (B, 2, 2049)
__device__ float g_h1 [BB * 32 * NF];         // gate conv1 out
__device__ float g_pooled[BB * 64];           // gate pooled sums (pre-mean)
__device__ int   g_ti [BB * 2];               // selected expert ids per slot
__device__ float g_tw [BB * 2];               // normalized top-k weights
__device__ float g_e1 [256 * 64 * L1E];       // expert conv1 out per slot
__device__ float g_e2 [256 * 128 * L2E];      // expert conv2 out per slot
__device__ float g_e3 [256 * 128 * L2E];      // expert conv3 out per slot
__device__ float2 g_twid[2048];               // W_4096^m, m in [0,2048)

// transposed weights: [(i*K + k) * Cout + o]
__device__ float g_gw2t[32 * 5 * 64];             // gate conv2
__device__ float g_ew2t[8 * 64 * 5 * 128];        // expert conv2 per expert
__device__ float g_ew3t[8 * 128 * 3 * 128];       // expert conv3 per expert

// ---------------- packed f32x2 helpers (FFMA2) -------------------------------
__device__ __forceinline__ unsigned long long pk2(float lo, float hi) {
    unsigned long long r;
    asm("mov.b64 %0, {%1, %2};" : "=l"(r) : "f"(lo), "f"(hi));
    return r;
}
__device__ __forceinline__ void ffma2(unsigned long long& d,
                                      unsigned long long a,
                                      unsigned long long b) {
    asm("fma.rn.f32x2 %0, %1, %2, %0;" : "+l"(d) : "l"(a), "l"(b));
}
__device__ __forceinline__ float2 upk2(unsigned long long v) {
    float2 f;
    asm("mov.b64 {%0, %1}, %2;" : "=f"(f.x), "=f"(f.y) : "l"(v));
    return f;
}

// ---------------- init + weight transposes ----------------------------------
__global__ void zero_pooled_kernel() {
    int i = blockIdx.x * blockDim.x + threadIdx.x;
    if (i < BB * 64) g_pooled[i] = 0.f;
}

__global__ void twid_kernel() {
    int m = blockIdx.x * blockDim.x + threadIdx.x;
    if (m < 2048) {
        float si, co;
        sincosf(-6.28318530717958647692f * (float)m / 4096.0f, &si, &co);
        g_twid[m] = make_float2(co, si);
    }
}

__global__ void t_gw2_kernel(const float* __restrict__ w2) {
    int idx = blockIdx.x * blockDim.x + threadIdx.x;   // 64*32*5 = 10240
    if (idx >= 64 * 32 * 5) return;
    int o = idx / 160;
    int ik = idx % 160;          // i*5+k
    g_gw2t[ik * 64 + o] = w2[o * 160 + ik];
}

__global__ void t_ew2_kernel(const float* __restrict__ ew2) {
    int idx = blockIdx.x * blockDim.x + threadIdx.x;   // 8*128*320
    if (idx >= 8 * 128 * 320) return;
    int e = idx / (128 * 320);
    int r = idx % (128 * 320);
    int o = r / 320;
    int ik = r % 320;
    g_ew2t[e * 40960 + ik * 128 + o] = ew2[idx];
}

__global__ void t_ew3_kernel(const float* __restrict__ ew3) {
    int idx = blockIdx.x * blockDim.x + threadIdx.x;   // 8*128*384
    if (idx >= 8 * 128 * 384) return;
    int e = idx / (128 * 384);
    int r = idx % (128 * 384);
    int o = r / 384;
    int ik = r % 384;
    g_ew3t[e * 49152 + ik * 128 + o] = ew3[idx];
}

// ---------------- Hann window + rfft(4096), ortho norm ----------------------
__global__ void fft_kernel(const float* __restrict__ x) {
    __shared__ float2 sd[LSEQ];
    const int b = blockIdx.x;
    const int tid = threadIdx.x;   // 512 threads
    const float* xr = x + b * LSEQ;
    const float twopi = 6.28318530717958647692f;

    for (int i = tid; i < LSEQ; i += 512) {
        float win = 0.5f * (1.0f - cosf(twopi * (float)i / (float)LSEQ));
        int r = (int)(__brev((unsigned)i) >> 20);   // 12-bit reversal
        sd[r] = make_float2(xr[i] * win, 0.f);
    }
    __syncthreads();

    for (int s = 1; s <= 12; s++) {
        int half = 1 << (s - 1);
        int shift = 12 - s;
        for (int j = tid; j < 2048; j += 512) {
            int pos = j & (half - 1);
            int i1 = ((j >> (s - 1)) << s) | pos;
            int i2 = i1 + half;
            float2 w = g_twid[pos << shift];   // (cos, sin) of -2*pi*pos/2^s
            float2 a = sd[i1], bv = sd[i2];
            float tr = bv.x * w.x - bv.y * w.y;
            float ti = bv.x * w.y + bv.y * w.x;
            sd[i1] = make_float2(a.x + tr, a.y + ti);
            sd[i2] = make_float2(a.x - tr, a.y - ti);
        }
        __syncthreads();
    }

    const float scale = 1.0f / 64.0f;   // 1/sqrt(4096), ortho norm
    for (int t = tid; t < NF; t += 512) {
        g_fft[b * 2 * NF + t]      = sd[t].x * scale;
        g_fft[b * 2 * NF + NF + t] = sd[t].y * scale;
    }
}

// ---------------- gate conv1: (2 -> 32, k=5, pad=2) -------------------------
__global__ void gconv1_kernel(const float* __restrict__ w,
                              const float* __restrict__ bias) {
    int idx = blockIdx.x * blockDim.x + threadIdx.x;
    if (idx >= BB * 32 * NF) return;
    int t = idx % NF;
    int o = (idx / NF) & 31;
    int b = idx / (NF * 32);
    const float* f0 = g_fft + b * 2 * NF;
    float acc = bias[o];
#pragma unroll
    for (int i = 0; i < 2; i++) {
#pragma unroll
        for (int k = 0; k < 5; k++) {
            int p = t + k - 2;
            float v = (p >= 0 && p < NF) ? f0[i * NF + p] : 0.f;
            acc += v * w[(o * 2 + i) * 5 + k];
        }
    }
    g_h1[idx] = fmaxf(acc, 0.f);
}

// ---------------- gate conv2 (32 -> 64, k=5, pad=2) + fused mean-pool -------
// block 512 = 32 channel-pairs x 16 pos-groups of 8; tile = 128 positions.
// FFMA2: lane handles channels (2c, 2c+1); weight pair = one LDG.64.
__global__ void __launch_bounds__(512) gconv2_pool_kernel(const float* __restrict__ b2) {
    __shared__ __align__(16) float sh[32 * 132];
    __shared__ float spool[64];
    const int b  = blockIdx.y;
    const int t0 = blockIdx.x * 128;
    const int tid = threadIdx.x;
    if (tid < 64) spool[tid] = 0.f;
    for (int idx = tid; idx < 32 * 132; idx += 512) {
        int ch = idx / 132, pl = idx % 132;
        int p = t0 + pl - 2;
        sh[idx] = (p >= 0 && p < NF) ? g_h1[(b * 32 + ch) * NF + p] : 0.f;
    }
    __syncthreads();

    const int c = tid & 31;       // channel pair -> channels 2c, 2c+1
    const int q = tid >> 5;       // 0..15, 8 positions each
    const float4* S4 = (const float4*)sh;
    const unsigned long long* WP = (const unsigned long long*)g_gw2t;
    unsigned long long acc[8];
#pragma unroll
    for (int j = 0; j < 8; j++) acc[j] = 0ULL;

#pragma unroll 4
    for (int i = 0; i < 32; i++) {
        float r[12];
#pragma unroll
        for (int m = 0; m < 3; m++) {
            float4 v = S4[i * 33 + q * 2 + m];
            r[4*m] = v.x; r[4*m+1] = v.y; r[4*m+2] = v.z; r[4*m+3] = v.w;
        }
        unsigned long long rp[12];
#pragma unroll
        for (int m = 0; m < 12; m++) rp[m] = pk2(r[m], r[m]);
#pragma unroll
        for (int k = 0; k < 5; k++) {
            unsigned long long wv = __ldg(&WP[(i * 5 + k) * 32 + c]);
#pragma unroll
            for (int j = 0; j < 8; j++) ffma2(acc[j], rp[j + k], wv);
        }
    }
    float b0 = b2[2 * c], b1 = b2[2 * c + 1];
    float l0 = 0.f, l1 = 0.f;
#pragma unroll
    for (int j = 0; j < 8; j++) {
        int t = t0 + q * 8 + j;
        if (t < NF) {
            float2 a = upk2(acc[j]);
            l0 += fmaxf(a.x + b0, 0.f);
            l1 += fmaxf(a.y + b1, 0.f);
        }
    }
    atomicAdd(&spool[2 * c], l0);
    atomicAdd(&spool[2 * c + 1], l1);
    __syncthreads();
    if (tid < 64) atomicAdd(&g_pooled[b * 64 + tid], spool[tid]);
}

// ---------------- gating MLP + softmax + aux + top-k ------------------------
__global__ void gate_kernel(const float* __restrict__ m_w1,
                            const float* __restrict__ m_b1,
                            const float* __restrict__ m_w2,
                            const float* __restrict__ m_b2,
                            float* __restrict__ d_out, int aux_idx) {
    __shared__ float sh_rw[128 * 8];
    __shared__ float sh_lg[128 * 8];
    const int b = threadIdx.x;   // 128 threads, one per batch row

    float p[64];
#pragma unroll
    for (int i = 0; i < 64; i++) p[i] = g_pooled[b * 64 + i] * (1.0f / 2049.0f);

    float lg[8];
#pragma unroll
    for (int e = 0; e < 8; e++) lg[e] = m_b2[e];
    for (int j = 0; j < 128; j++) {
        float h = m_b1[j];
#pragma unroll
        for (int i = 0; i < 64; i++) h += p[i] * m_w1[j * 64 + i];
        h = fmaxf(h, 0.f);
#pragma unroll
        for (int e = 0; e < 8; e++) lg[e] += h * m_w2[e * 128 + j];
    }

    float mx = lg[0];
#pragma unroll
    for (int e = 1; e < 8; e++) mx = fmaxf(mx, lg[e]);
    float rw[8], s = 0.f;
#pragma unroll
    for (int e = 0; e < 8; e++) { rw[e] = expf(lg[e] - mx); s += rw[e]; }
#pragma unroll
    for (int e = 0; e < 8; e++) rw[e] /= s;

#pragma unroll
    for (int e = 0; e < 8; e++) {
        sh_rw[b * 8 + e] = rw[e];
        sh_lg[b * 8 + e] = lg[e];
    }
    __syncthreads();
    if (b == 0) {
        float aux = 0.f;
#pragma unroll
        for (int e = 0; e < 8; e++) {
            float sr = 0.f, sl = 0.f;
            for (int bb = 0; bb < 128; bb++) {
                sr += sh_rw[bb * 8 + e];
                sl += sh_lg[bb * 8 + e];
            }
            aux += (sr * (1.f / 128.f)) * (sl * (1.f / 128.f));
        }
        d_out[aux_idx] = 0.01f * 8.f * aux;
    }

    // top-2, ties -> lowest index (strict > keeps first max)
    int e1 = 0;
#pragma unroll
    for (int e = 1; e < 8; e++) if (rw[e] > rw[e1]) e1 = e;
    int e2 = (e1 == 0) ? 1 : 0;
#pragma unroll
    for (int e = 0; e < 8; e++) if (e != e1 && rw[e] > rw[e2]) e2 = e;
    float w1v = rw[e1], w2v = rw[e2], ss = w1v + w2v;
    g_ti[b * 2]     = e1;
    g_ti[b * 2 + 1] = e2;
    g_tw[b * 2]     = w1v / ss;
    g_tw[b * 2 + 1] = w2v / ss;
}

// ---------------- expert conv1: (2 -> 64, k=7, s=2, pad=3) ------------------
__global__ void econv1_kernel(const float* __restrict__ ew1,
                              const float* __restrict__ eb1) {
    int idx = blockIdx.x * blockDim.x + threadIdx.x;
    if (idx >= 256 * 64 * L1E) return;
    int t = idx % L1E;
    int o = (idx / L1E) & 63;
    int slot = idx / (L1E * 64);
    int b = slot >> 1;
    int e = g_ti[slot];
    const float* f0 = g_fft + b * 2 * NF;
    const float* wb = ew1 + (e * 64 + o) * 2 * 7;
    float acc = eb1[e * 64 + o];
#pragma unroll
    for (int i = 0; i < 2; i++) {
#pragma unroll
        for (int k = 0; k < 7; k++) {
            int p = 2 * t + k - 3;
            float v = (p >= 0 && p < NF) ? f0[i * NF + p] : 0.f;
            acc += v * wb[i * 7 + k];
        }
    }
    g_e1[idx] = fmaxf(acc, 0.f);
}

// ---------------- expert conv2: (64 -> 128, k=5, s=2, pad=2) ----------------
// block 512 = 64 channel-pairs x 8 pos-groups of 8; tile = 64 positions.
__global__ void __launch_bounds__(512) econv2_kernel(const float* __restrict__ eb2) {
    __shared__ __align__(16) float sh[64 * 136];
    const int slot = blockIdx.y;
    const int t0 = blockIdx.x * 64;
    const int tid = threadIdx.x;
    const int e = g_ti[slot];
    for (int idx = tid; idx < 64 * 136; idx += 512) {
        int ch = idx / 136, pl = idx % 136;
        int p = 2 * t0 - 2 + pl;
        sh[idx] = (p >= 0 && p < L1E) ? g_e1[(slot * 64 + ch) * L1E + p] : 0.f;
    }
    __syncthreads();

    const int c = tid & 63;       // channel pair -> channels 2c, 2c+1
    const int q = tid >> 6;       // 0..7, 8 positions each
    const float4* S4 = (const float4*)sh;
    const unsigned long long* WP = (const unsigned long long*)(g_ew2t + e * 40960);
    unsigned long long acc[8];
#pragma unroll
    for (int j = 0; j < 8; j++) acc[j] = 0ULL;

#pragma unroll 2
    for (int i = 0; i < 64; i++) {
        float r[20];
#pragma unroll
        for (int m = 0; m < 5; m++) {
            float4 v = S4[i * 34 + q * 4 + m];
            r[4*m] = v.x; r[4*m+1] = v.y; r[4*m+2] = v.z; r[4*m+3] = v.w;
        }
        unsigned long long rp[19];
#pragma unroll
        for (int m = 0; m < 19; m++) rp[m] = pk2(r[m], r[m]);
#pragma unroll
        for (int k = 0; k < 5; k++) {
            unsigned long long wv = __ldg(&WP[(i * 5 + k) * 64 + c]);
#pragma unroll
            for (int j = 0; j < 8; j++) ffma2(acc[j], rp[2 * j + k], wv);
        }
    }
    float b0 = eb2[e * 128 + 2 * c], b1 = eb2[e * 128 + 2 * c + 1];
#pragma unroll
    for (int j = 0; j < 8; j++) {
        int t = t0 + q * 8 + j;
        if (t < L2E) {
            float2 a = upk2(acc[j]);
            g_e2[(slot * 128 + 2 * c)     * L2E + t] = fmaxf(a.x + b0, 0.f);
            g_e2[(slot * 128 + 2 * c + 1) * L2E + t] = fmaxf(a.y + b1, 0.f);
        }
    }
}

// ---------------- expert conv3: (128 -> 128, k=3, s=1, pad=1) ---------------
// block 512 = 64 channel-pairs x 8 pos-groups of 8; tile = 64 positions.
__global__ void __launch_bounds__(512) econv3_kernel(const float* __restrict__ eb3) {
    __shared__ __align__(16) float sh[128 * 68];
    const int slot = blockIdx.y;
    const int t0 = blockIdx.x * 64;
    const int tid = threadIdx.x;
    const int e = g_ti[slot];
    for (int idx = tid; idx < 128 * 68; idx += 512) {
        int ch = idx / 68, pl = idx % 68;
        int p = t0 - 1 + pl;
        sh[idx] = (p >= 0 && p < L2E) ? g_e2[(slot * 128 + ch) * L2E + p] : 0.f;
    }
    __syncthreads();

    const int c = tid & 63;       // channel pair -> channels 2c, 2c+1
    const int q = tid >> 6;       // 0..7, 8 positions each
    const float4* S4 = (const float4*)sh;
    const unsigned long long* WP = (const unsigned long long*)(g_ew3t + e * 49152);
    unsigned long long acc[8];
#pragma unroll
    for (int j = 0; j < 8; j++) acc[j] = 0ULL;

#pragma unroll 4
    for (int i = 0; i < 128; i++) {
        float r[12];
#pragma unroll
        for (int m = 0; m < 3; m++) {
            float4 v = S4[i * 17 + q * 2 + m];
            r[4*m] = v.x; r[4*m+1] = v.y; r[4*m+2] = v.z; r[4*m+3] = v.w;
        }
        unsigned long long rp[10];
#pragma unroll
        for (int m = 0; m < 10; m++) rp[m] = pk2(r[m], r[m]);
#pragma unroll
        for (int k = 0; k < 3; k++) {
            unsigned long long wv = __ldg(&WP[(i * 3 + k) * 64 + c]);
#pragma unroll
            for (int j = 0; j < 8; j++) ffma2(acc[j], rp[j + k], wv);
        }
    }
    float b0 = eb3[e * 128 + 2 * c], b1 = eb3[e * 128 + 2 * c + 1];
#pragma unroll
    for (int j = 0; j < 8; j++) {
        int t = t0 + q * 8 + j;
        if (t < L2E) {
            float2 a = upk2(acc[j]);
            g_e3[(slot * 128 + 2 * c)     * L2E + t] = fmaxf(a.x + b0, 0.f);
            g_e3[(slot * 128 + 2 * c + 1) * L2E + t] = fmaxf(a.y + b1, 0.f);
        }
    }
}

// ---------------- combine top-2 + adaptive max-pool 513 -> 256 --------------
__global__ void combine_kernel(float* __restrict__ out) {
    int idx = blockIdx.x * blockDim.x + threadIdx.x;
    if (idx >= BB * 128 * OUTS) return;
    int i = idx & 255;
    int c = (idx >> 8) & 127;
    int b = idx >> 15;
    int start = (i * L2E) >> 8;                 // floor(i*513/256)
    int end   = ((i + 1) * L2E + 255) >> 8;     // ceil((i+1)*513/256)
    float w0 = g_tw[b * 2], w1 = g_tw[b * 2 + 1];
    const float* p0 = g_e3 + ((size_t)(b * 2)     * 128 + c) * L2E;
    const float* p1 = g_e3 + ((size_t)(b * 2 + 1) * 128 + c) * L2E;
    float m = -3.402823466e38f;
    for (int t = start; t < end; t++) {
        float v = w0 * p0[t] + w1 * p1[t];
        m = fmaxf(m, v);
    }
    out[idx] = m;
}

// ---------------- launch ----------------------------------------------------
extern "C" void kernel_launch(void* const* d_in, const int* in_sizes, int n_in,
                              void* d_out, int out_size) {
    const float* x    = (const float*)d_in[0];
    const float* g_w1 = (const float*)d_in[1];
    const float* g_b1 = (const float*)d_in[2];
    const float* g_w2 = (const float*)d_in[3];
    const float* g_b2 = (const float*)d_in[4];
    const float* m_w1 = (const float*)d_in[5];
    const float* m_b1 = (const float*)d_in[6];
    const float* m_w2 = (const float*)d_in[7];
    const float* m_b2 = (const float*)d_in[8];
    const float* ew1  = (const float*)d_in[9];
    const float* eb1  = (const float*)d_in[10];
    const float* ew2  = (const float*)d_in[11];
    const float* eb2  = (const float*)d_in[12];
    const float* ew3  = (const float*)d_in[13];
    const float* eb3  = (const float*)d_in[14];
    float* out = (float*)d_out;

    zero_pooled_kernel<<<(BB * 64 + 255) / 256, 256>>>();
    twid_kernel<<<8, 256>>>();
    t_gw2_kernel<<<(64 * 32 * 5 + 255) / 256, 256>>>(g_w2);
    t_ew2_kernel<<<(8 * 128 * 320 + 255) / 256, 256>>>(ew2);
    t_ew3_kernel<<<(8 * 128 * 384 + 255) / 256, 256>>>(ew3);
    fft_kernel<<<BB, 512>>>(x);
    gconv1_kernel<<<(BB * 32 * NF + 255) / 256, 256>>>(g_w1, g_b1);
    gconv2_pool_kernel<<<dim3(17, BB), 512>>>(g_b2);
    gate_kernel<<<1, 128>>>(m_w1, m_b1, m_w2, m_b2, out, out_size - 1);
    econv1_kernel<<<(256 * 64 * L1E + 255) / 256, 256>>>(ew1, eb1);
    econv2_kernel<<<dim3(9, 256), 512>>>(eb2);
    econv3_kernel<<<dim3(9, 256), 512>>>(eb3);
    combine_kernel<<<(BB * 128 * OUTS + 255) / 256, 256>>>(out);
}

// round 10
// speedup vs baseline: 1.0394x; 1.0394x over previous
#include <cuda_runtime.h>
#include <math.h>

#define BB    128
#define LSEQ  4096
#define NF    2049
#define L1E   1025
#define L2E   513
#define OUTS  256
#define WT    48      // econv3 outputs per block tile
#define WJ    12      // winograd tiles per block

// ---------------- scratch (device globals; no allocations allowed) ----------
__device__ float g_fft[BB * 2 * NF];          // windowed rfft, (B, 2, 2049)
__device__ float g_h1 [BB * 32 * NF];         // gate conv1 out
__device__ float g_pooled[BB * 64];           // gate pooled sums (pre-mean)
__device__ int   g_ti [BB * 2];               // selected expert ids per slot
__device__ float g_tw [BB * 2];               // normalized top-k weights
__device__ float g_e1 [256 * 64 * L1E];       // expert conv1 out per slot
__device__ float g_e2 [256 * 128 * L2E];      // expert conv2 out per slot
__device__ float g_e3 [256 * 128 * L2E];      // expert conv3 out per slot
__device__ float2 g_twid[2048];               // W_4096^m, m in [0,2048)

// transposed weights
__device__ float g_gw2t[32 * 5 * 64];             // gate conv2 [(i*5+k)*64+o]
__device__ float g_ew2t[8 * 64 * 5 * 128];        // expert conv2 [(i*5+k)*128+o]
__device__ float g_ew3w[8 * 128 * 6 * 128];       // econv3 winograd [(cin*6+i)*128+o]

// ---------------- init + weight transforms ----------------------------------
__global__ void zero_pooled_kernel() {
    int i = blockIdx.x * blockDim.x + threadIdx.x;
    if (i < BB * 64) g_pooled[i] = 0.f;
}

__global__ void twid_kernel() {
    int m = blockIdx.x * blockDim.x + threadIdx.x;
    if (m < 2048) {
        float si, co;
        sincosf(-6.28318530717958647692f * (float)m / 4096.0f, &si, &co);
        g_twid[m] = make_float2(co, si);
    }
}

__global__ void t_gw2_kernel(const float* __restrict__ w2) {
    int idx = blockIdx.x * blockDim.x + threadIdx.x;   // 64*32*5 = 10240
    if (idx >= 64 * 32 * 5) return;
    int o = idx / 160;
    int ik = idx % 160;          // i*5+k
    g_gw2t[ik * 64 + o] = w2[o * 160 + ik];
}

__global__ void t_ew2_kernel(const float* __restrict__ ew2) {
    int idx = blockIdx.x * blockDim.x + threadIdx.x;   // 8*128*320
    if (idx >= 8 * 128 * 320) return;
    int e = idx / (128 * 320);
    int r = idx % (128 * 320);
    int o = r / 320;
    int ik = r % 320;
    g_ew2t[e * 40960 + ik * 128 + o] = ew2[idx];
}

// winograd F(4,3) weight transform: m = G w
__global__ void t_ew3w_kernel(const float* __restrict__ ew3) {
    int idx = blockIdx.x * blockDim.x + threadIdx.x;   // 8*128*128
    if (idx >= 8 * 128 * 128) return;
    int e = idx / 16384;
    int r = idx % 16384;
    int cin = r / 128;
    int o = r % 128;
    const float* w = ew3 + (((size_t)e * 128 + o) * 128 + cin) * 3;
    float w0 = w[0], w1 = w[1], w2v = w[2];
    float m0 = 0.25f * w0;
    float m1 = -(w0 + w1 + w2v) * (1.f / 6.f);
    float m2 = (-w0 + w1 - w2v) * (1.f / 6.f);
    float m3 = (w0 + 2.f * w1 + 4.f * w2v) * (1.f / 24.f);
    float m4 = (w0 - 2.f * w1 + 4.f * w2v) * (1.f / 24.f);
    float m5 = w2v;
    float* dst = g_ew3w + e * 98304 + (cin * 6) * 128 + o;
    dst[0]   = m0; dst[128] = m1; dst[256] = m2;
    dst[384] = m3; dst[512] = m4; dst[640] = m5;
}

// ---------------- Hann window + rfft(4096), ortho norm ----------------------
__global__ void fft_kernel(const float* __restrict__ x) {
    __shared__ float2 sd[LSEQ];
    const int b = blockIdx.x;
    const int tid = threadIdx.x;   // 512 threads
    const float* xr = x + b * LSEQ;
    const float twopi = 6.28318530717958647692f;

    for (int i = tid; i < LSEQ; i += 512) {
        float win = 0.5f * (1.0f - cosf(twopi * (float)i / (float)LSEQ));
        int r = (int)(__brev((unsigned)i) >> 20);   // 12-bit reversal
        sd[r] = make_float2(xr[i] * win, 0.f);
    }
    __syncthreads();

    for (int s = 1; s <= 12; s++) {
        int half = 1 << (s - 1);
        int shift = 12 - s;
        for (int j = tid; j < 2048; j += 512) {
            int pos = j & (half - 1);
            int i1 = ((j >> (s - 1)) << s) | pos;
            int i2 = i1 + half;
            float2 w = g_twid[pos << shift];   // (cos, sin) of -2*pi*pos/2^s
            float2 a = sd[i1], bv = sd[i2];
            float tr = bv.x * w.x - bv.y * w.y;
            float ti = bv.x * w.y + bv.y * w.x;
            sd[i1] = make_float2(a.x + tr, a.y + ti);
            sd[i2] = make_float2(a.x - tr, a.y - ti);
        }
        __syncthreads();
    }

    const float scale = 1.0f / 64.0f;   // 1/sqrt(4096), ortho norm
    for (int t = tid; t < NF; t += 512) {
        g_fft[b * 2 * NF + t]      = sd[t].x * scale;
        g_fft[b * 2 * NF + NF + t] = sd[t].y * scale;
    }
}

// ---------------- gate conv1: (2 -> 32, k=5, pad=2) -------------------------
__global__ void gconv1_kernel(const float* __restrict__ w,
                              const float* __restrict__ bias) {
    int idx = blockIdx.x * blockDim.x + threadIdx.x;
    if (idx >= BB * 32 * NF) return;
    int t = idx % NF;
    int o = (idx / NF) & 31;
    int b = idx / (NF * 32);
    const float* f0 = g_fft + b * 2 * NF;
    float acc = bias[o];
#pragma unroll
    for (int i = 0; i < 2; i++) {
#pragma unroll
        for (int k = 0; k < 5; k++) {
            int p = t + k - 2;
            float v = (p >= 0 && p < NF) ? f0[i * NF + p] : 0.f;
            acc += v * w[(o * 2 + i) * 5 + k];
        }
    }
    g_h1[idx] = fmaxf(acc, 0.f);
}

// ---------------- gate conv2 (32 -> 64, k=5, pad=2) + fused mean-pool -------
// block 512: o = tid&63, q = tid>>6 in 0..7, 16 positions each; tile 128.
__global__ void __launch_bounds__(512) gconv2_pool_kernel(const float* __restrict__ b2) {
    __shared__ __align__(16) float sh[32 * 132];
    __shared__ float spool[64];
    const int b  = blockIdx.y;
    const int t0 = blockIdx.x * 128;
    const int tid = threadIdx.x;
    if (tid < 64) spool[tid] = 0.f;
    for (int idx = tid; idx < 32 * 132; idx += 512) {
        int ch = idx / 132, pl = idx % 132;
        int p = t0 + pl - 2;
        sh[idx] = (p >= 0 && p < NF) ? g_h1[(b * 32 + ch) * NF + p] : 0.f;
    }
    __syncthreads();

    const int o = tid & 63;
    const int q = tid >> 6;
    const float4* S4 = (const float4*)sh;
    float acc[16];
#pragma unroll
    for (int j = 0; j < 16; j++) acc[j] = 0.f;

#pragma unroll 4
    for (int i = 0; i < 32; i++) {
        float r[20];
#pragma unroll
        for (int m = 0; m < 5; m++) {
            float4 v = S4[i * 33 + q * 4 + m];
            r[4*m] = v.x; r[4*m+1] = v.y; r[4*m+2] = v.z; r[4*m+3] = v.w;
        }
#pragma unroll
        for (int k = 0; k < 5; k++) {
            float wv = __ldg(&g_gw2t[(i * 5 + k) * 64 + o]);
#pragma unroll
            for (int j = 0; j < 16; j++) acc[j] += wv * r[j + k];
        }
    }
    float bo = b2[o];
    float local = 0.f;
#pragma unroll
    for (int j = 0; j < 16; j++) {
        int t = t0 + q * 16 + j;
        if (t < NF) local += fmaxf(acc[j] + bo, 0.f);
    }
    atomicAdd(&spool[o], local);
    __syncthreads();
    if (tid < 64) atomicAdd(&g_pooled[b * 64 + tid], spool[tid]);
}

// ---------------- gating MLP + softmax + aux + top-k ------------------------
__global__ void gate_kernel(const float* __restrict__ m_w1,
                            const float* __restrict__ m_b1,
                            const float* __restrict__ m_w2,
                            const float* __restrict__ m_b2,
                            float* __restrict__ d_out, int aux_idx) {
    __shared__ float sh_rw[128 * 8];
    __shared__ float sh_lg[128 * 8];
    const int b = threadIdx.x;   // 128 threads, one per batch row

    float p[64];
#pragma unroll
    for (int i = 0; i < 64; i++) p[i] = g_pooled[b * 64 + i] * (1.0f / 2049.0f);

    float lg[8];
#pragma unroll
    for (int e = 0; e < 8; e++) lg[e] = m_b2[e];
    for (int j = 0; j < 128; j++) {
        float h = m_b1[j];
#pragma unroll
        for (int i = 0; i < 64; i++) h += p[i] * m_w1[j * 64 + i];
        h = fmaxf(h, 0.f);
#pragma unroll
        for (int e = 0; e < 8; e++) lg[e] += h * m_w2[e * 128 + j];
    }

    float mx = lg[0];
#pragma unroll
    for (int e = 1; e < 8; e++) mx = fmaxf(mx, lg[e]);
    float rw[8], s = 0.f;
#pragma unroll
    for (int e = 0; e < 8; e++) { rw[e] = expf(lg[e] - mx); s += rw[e]; }
#pragma unroll
    for (int e = 0; e < 8; e++) rw[e] /= s;

#pragma unroll
    for (int e = 0; e < 8; e++) {
        sh_rw[b * 8 + e] = rw[e];
        sh_lg[b * 8 + e] = lg[e];
    }
    __syncthreads();
    if (b == 0) {
        float aux = 0.f;
#pragma unroll
        for (int e = 0; e < 8; e++) {
            float sr = 0.f, sl = 0.f;
            for (int bb = 0; bb < 128; bb++) {
                sr += sh_rw[bb * 8 + e];
                sl += sh_lg[bb * 8 + e];
            }
            aux += (sr * (1.f / 128.f)) * (sl * (1.f / 128.f));
        }
        d_out[aux_idx] = 0.01f * 8.f * aux;
    }

    // top-2, ties -> lowest index (strict > keeps first max)
    int e1 = 0;
#pragma unroll
    for (int e = 1; e < 8; e++) if (rw[e] > rw[e1]) e1 = e;
    int e2 = (e1 == 0) ? 1 : 0;
#pragma unroll
    for (int e = 0; e < 8; e++) if (e != e1 && rw[e] > rw[e2]) e2 = e;
    float w1v = rw[e1], w2v = rw[e2], ss = w1v + w2v;
    g_ti[b * 2]     = e1;
    g_ti[b * 2 + 1] = e2;
    g_tw[b * 2]     = w1v / ss;
    g_tw[b * 2 + 1] = w2v / ss;
}

// ---------------- expert conv1: (2 -> 64, k=7, s=2, pad=3) ------------------
__global__ void econv1_kernel(const float* __restrict__ ew1,
                              const float* __restrict__ eb1) {
    int idx = blockIdx.x * blockDim.x + threadIdx.x;
    if (idx >= 256 * 64 * L1E) return;
    int t = idx % L1E;
    int o = (idx / L1E) & 63;
    int slot = idx / (L1E * 64);
    int b = slot >> 1;
    int e = g_ti[slot];
    const float* f0 = g_fft + b * 2 * NF;
    const float* wb = ew1 + (e * 64 + o) * 2 * 7;
    float acc = eb1[e * 64 + o];
#pragma unroll
    for (int i = 0; i < 2; i++) {
#pragma unroll
        for (int k = 0; k < 7; k++) {
            int p = 2 * t + k - 3;
            float v = (p >= 0 && p < NF) ? f0[i * NF + p] : 0.f;
            acc += v * wb[i * 7 + k];
        }
    }
    g_e1[idx] = fmaxf(acc, 0.f);
}

// ---------------- expert conv2: (64 -> 128, k=5, s=2, pad=2) ----------------
// block 512: o = tid&127, q = tid>>7 in 0..3, 16 outputs each.
__global__ void __launch_bounds__(512) econv2_kernel(const float* __restrict__ eb2) {
    __shared__ __align__(16) float sh[64 * 136];
    const int slot = blockIdx.y;
    const int t0 = blockIdx.x * 64;
    const int tid = threadIdx.x;
    const int e = g_ti[slot];
    for (int idx = tid; idx < 64 * 136; idx += 512) {
        int ch = idx / 136, pl = idx % 136;
        int p = 2 * t0 - 2 + pl;
        sh[idx] = (p >= 0 && p < L1E) ? g_e1[(slot * 64 + ch) * L1E + p] : 0.f;
    }
    __syncthreads();

    const int o = tid & 127;
    const int q = tid >> 7;
    const float4* S4 = (const float4*)sh;
    const float* wt = g_ew2t + e * 40960;
    float acc[16];
#pragma unroll
    for (int j = 0; j < 16; j++) acc[j] = 0.f;

#pragma unroll 2
    for (int i = 0; i < 64; i++) {
        float r[36];
#pragma unroll
        for (int m = 0; m < 9; m++) {
            float4 v = S4[i * 34 + q * 8 + m];
            r[4*m] = v.x; r[4*m+1] = v.y; r[4*m+2] = v.z; r[4*m+3] = v.w;
        }
#pragma unroll
        for (int k = 0; k < 5; k++) {
            float wv = __ldg(&wt[(i * 5 + k) * 128 + o]);
#pragma unroll
            for (int j = 0; j < 16; j++) acc[j] += wv * r[2 * j + k];
        }
    }
    float bo = eb2[e * 128 + o];
#pragma unroll
    for (int j = 0; j < 16; j++) {
        int t = t0 + q * 16 + j;
        if (t < L2E) g_e2[(slot * 128 + o) * L2E + t] = fmaxf(acc[j] + bo, 0.f);
    }
}

// ---------------- expert conv3: Winograd F(4,3), (128 -> 128, k=3, pad=1) ---
// block 256: o = tid&127, q = tid>>7 in 0..1, 6 win-tiles (24 outputs) each.
// Tile = 48 outputs = 12 win-tiles. zs[cin][i=0..5][tile=0..11].
__global__ void __launch_bounds__(256) econv3_wino_kernel(const float* __restrict__ eb3) {
    __shared__ float zs[128 * 72];
    const int slot = blockIdx.y;
    const int t0 = blockIdx.x * WT;
    const int tid = threadIdx.x;
    const int e = g_ti[slot];

    // phase 1: input transform z = B^T x, 128*12 vectors, 6 per thread
    for (int v = tid; v < 128 * WJ; v += 256) {
        int cin = v / WJ, j = v % WJ;
        const float* src = g_e2 + ((size_t)slot * 128 + cin) * L2E;
        int p = t0 + 4 * j - 1;
        float x0 = (p + 0 >= 0 && p + 0 < L2E) ? src[p + 0] : 0.f;
        float x1 = (p + 1 >= 0 && p + 1 < L2E) ? src[p + 1] : 0.f;
        float x2 = (p + 2 >= 0 && p + 2 < L2E) ? src[p + 2] : 0.f;
        float x3 = (p + 3 >= 0 && p + 3 < L2E) ? src[p + 3] : 0.f;
        float x4 = (p + 4 >= 0 && p + 4 < L2E) ? src[p + 4] : 0.f;
        float x5 = (p + 5 >= 0 && p + 5 < L2E) ? src[p + 5] : 0.f;
        float* zb = zs + cin * 72 + j;
        zb[0]  = 4.f * x0 - 5.f * x2 + x4;
        zb[12] = -4.f * x1 - 4.f * x2 + x3 + x4;
        zb[24] =  4.f * x1 - 4.f * x2 - x3 + x4;
        zb[36] = -2.f * x1 - x2 + 2.f * x3 + x4;
        zb[48] =  2.f * x1 - x2 - 2.f * x3 + x4;
        zb[60] =  4.f * x1 - 5.f * x3 + x5;
    }
    __syncthreads();

    const int o = tid & 127;
    const int q = tid >> 7;          // 0..1, win-tiles 6q..6q+5
    const float* wt = g_ew3w + e * 98304;
    float U[6][6];                   // [i][tile]
#pragma unroll
    for (int i = 0; i < 6; i++)
#pragma unroll
        for (int t = 0; t < 6; t++) U[i][t] = 0.f;

    for (int cin = 0; cin < 128; cin++) {
#pragma unroll
        for (int i = 0; i < 6; i++) {
            float wv = __ldg(&wt[(cin * 6 + i) * 128 + o]);
            const float2* zp = (const float2*)(zs + cin * 72 + i * 12 + 6 * q);
            float2 a0 = zp[0], a1 = zp[1], a2 = zp[2];
            U[i][0] += wv * a0.x; U[i][1] += wv * a0.y;
            U[i][2] += wv * a1.x; U[i][3] += wv * a1.y;
            U[i][4] += wv * a2.x; U[i][5] += wv * a2.y;
        }
    }

    float bo = eb3[e * 128 + o];
    float* dst = g_e3 + ((size_t)slot * 128 + o) * L2E;
#pragma unroll
    for (int t = 0; t < 6; t++) {
        float U0 = U[0][t], U1 = U[1][t], U2 = U[2][t];
        float U3 = U[3][t], U4 = U[4][t], U5 = U[5][t];
        float y0 = U0 + U1 + U2 + U3 + U4;
        float y1 = U1 - U2 + 2.f * (U3 - U4);
        float y2 = U1 + U2 + 4.f * (U3 + U4);
        float y3 = U1 - U2 + 8.f * (U3 - U4) + U5;
        int tb = t0 + (q * 6 + t) * 4;
        if (tb + 0 < L2E) dst[tb + 0] = fmaxf(y0 + bo, 0.f);
        if (tb + 1 < L2E) dst[tb + 1] = fmaxf(y1 + bo, 0.f);
        if (tb + 2 < L2E) dst[tb + 2] = fmaxf(y2 + bo, 0.f);
        if (tb + 3 < L2E) dst[tb + 3] = fmaxf(y3 + bo, 0.f);
    }
}

// ---------------- combine top-2 + adaptive max-pool 513 -> 256 --------------
__global__ void combine_kernel(float* __restrict__ out) {
    int idx = blockIdx.x * blockDim.x + threadIdx.x;
    if (idx >= BB * 128 * OUTS) return;
    int i = idx & 255;
    int c = (idx >> 8) & 127;
    int b = idx >> 15;
    int start = (i * L2E) >> 8;                 // floor(i*513/256)
    int end   = ((i + 1) * L2E + 255) >> 8;     // ceil((i+1)*513/256)
    float w0 = g_tw[b * 2], w1 = g_tw[b * 2 + 1];
    const float* p0 = g_e3 + ((size_t)(b * 2)     * 128 + c) * L2E;
    const float* p1 = g_e3 + ((size_t)(b * 2 + 1) * 128 + c) * L2E;
    float m = -3.402823466e38f;
    for (int t = start; t < end; t++) {
        float v = w0 * p0[t] + w1 * p1[t];
        m = fmaxf(m, v);
    }
    out[idx] = m;
}

// ---------------- launch ----------------------------------------------------
extern "C" void kernel_launch(void* const* d_in, const int* in_sizes, int n_in,
                              void* d_out, int out_size) {
    const float* x    = (const float*)d_in[0];
    const float* g_w1 = (const float*)d_in[1];
    const float* g_b1 = (const float*)d_in[2];
    const float* g_w2 = (const float*)d_in[3];
    const float* g_b2 = (const float*)d_in[4];
    const float* m_w1 = (const float*)d_in[5];
    const float* m_b1 = (const float*)d_in[6];
    const float* m_w2 = (const float*)d_in[7];
    const float* m_b2 = (const float*)d_in[8];
    const float* ew1  = (const float*)d_in[9];
    const float* eb1  = (const float*)d_in[10];
    const float* ew2  = (const float*)d_in[11];
    const float* eb2  = (const float*)d_in[12];
    const float* ew3  = (const float*)d_in[13];
    const float* eb3  = (const float*)d_in[14];
    float* out = (float*)d_out;

    zero_pooled_kernel<<<(BB * 64 + 255) / 256, 256>>>();
    twid_kernel<<<8, 256>>>();
    t_gw2_kernel<<<(64 * 32 * 5 + 255) / 256, 256>>>(g_w2);
    t_ew2_kernel<<<(8 * 128 * 320 + 255) / 256, 256>>>(ew2);
    t_ew3w_kernel<<<(8 * 128 * 128 + 255) / 256, 256>>>(ew3);
    fft_kernel<<<BB, 512>>>(x);
    gconv1_kernel<<<(BB * 32 * NF + 255) / 256, 256>>>(g_w1, g_b1);
    gconv2_pool_kernel<<<dim3(17, BB), 512>>>(g_b2);
    gate_kernel<<<1, 128>>>(m_w1, m_b1, m_w2, m_b2, out, out_size - 1);
    econv1_kernel<<<(256 * 64 * L1E + 255) / 256, 256>>>(ew1, eb1);
    econv2_kernel<<<dim3(9, 256), 512>>>(eb2);
    econv3_wino_kernel<<<dim3(11, 256), 256>>>(eb3);
    combine_kernel<<<(BB * 128 * OUTS + 255) / 256, 256>>>(out);
}